// round 14
// baseline (speedup 1.0000x reference)
#include <cuda_runtime.h>
#include <cuda_bf16.h>
#include <cstdint>
#include <math.h>

// Problem constants
constexpr int M_ROWS = 65536;   // B*S*G
constexpr int N_V    = 320;
constexpr int K_D    = 384;
constexpr int OUT_D  = 768;
constexpr int GV     = 640;
constexpr float EPS_G  = 1e-10f;
constexpr float MARGIN = 0.405f;

// Device-global scratch (no allocation allowed)
__device__ __nv_bfloat16 g_z_bf16[M_ROWS * K_D];
__device__ __nv_bfloat16 g_Wt_bf16[N_V * K_D];   // W_logits^T bf16 [320][384]
__device__ float         g_Wt_f32 [N_V * K_D];   // W_logits^T fp32
__device__ float         g_E[GV * OUT_D];        // codebook@W_out fused table
__device__ float2        g_gtab[1280];           // gumbel secant-line table

__device__ __forceinline__ float gumbel_acc(float u) {
    return -logf(-logf(u + EPS_G) + EPS_G);
}
__device__ __forceinline__ void two_sum(float& s, float& c, float v) {
    float t  = s + v;
    float bv = t - s;
    float err = (s - (t - bv)) + (v - bv);
    s = t; c += err;
}
// monotonic float<->uint key for atomicMax-based float max
__device__ __forceinline__ uint32_t fkey(float f) {
    uint32_t b = __float_as_uint(f);
    return (b & 0x80000000u) ? ~b : (b | 0x80000000u);
}
__device__ __forceinline__ float funkey(uint32_t k) {
    uint32_t b = (k & 0x80000000u) ? (k & 0x7FFFFFFFu) : ~k;
    return __uint_as_float(b);
}

__device__ __forceinline__ void ldsm_x4(uint32_t* r, const void* p) {
    uint32_t addr = (uint32_t)__cvta_generic_to_shared(p);
    asm volatile("ldmatrix.sync.aligned.m8n8.x4.shared.b16 {%0,%1,%2,%3}, [%4];\n"
        : "=r"(r[0]), "=r"(r[1]), "=r"(r[2]), "=r"(r[3]) : "r"(addr));
}
__device__ __forceinline__ void mma_bf16(float* c, const uint32_t* a, const uint32_t* b) {
    asm volatile("mma.sync.aligned.m16n8k16.row.col.f32.bf16.bf16.f32 "
        "{%0,%1,%2,%3}, {%4,%5,%6,%7}, {%8,%9}, {%0,%1,%2,%3};\n"
        : "+f"(c[0]), "+f"(c[1]), "+f"(c[2]), "+f"(c[3])
        : "r"(a[0]), "r"(a[1]), "r"(a[2]), "r"(a[3]), "r"(b[0]), "r"(b[1]));
}
__device__ __forceinline__ void cp16(void* dst_smem, const void* src) {
    uint32_t d = (uint32_t)__cvta_generic_to_shared(dst_smem);
    asm volatile("cp.async.cg.shared.global [%0], [%1], 16;\n" :: "r"(d), "l"(src));
}
#define CP_COMMIT() asm volatile("cp.async.commit_group;\n")
#define CP_WAIT1()  asm volatile("cp.async.wait_group 1;\n")

// ---------------------------------------------------------------------------
// Kernel 0a: fused prep — b0: gumbel table; b1..480: W^T; b481..720: E GEMM
// ---------------------------------------------------------------------------
__global__ __launch_bounds__(256) void prep_kernel(
    const float* __restrict__ W, const float* __restrict__ CB,
    const float* __restrict__ Wout)
{
    __shared__ float As2[32][17];
    __shared__ float Bs2[16][68];
    const int b = blockIdx.x;
    const int t = threadIdx.x;

    if (b == 0) {
        // secant-line table of gumbel(u) over u-bit bins (128 bins/octave)
        for (int i = t; i < 1280; i += 256) {
            uint32_t bits0 = (uint32_t)(14976 + i) << 16;
            float u0 = __uint_as_float(bits0);
            float u1 = __uint_as_float(bits0 + 0x10000u);
            float g0 = gumbel_acc(u0);
            float g1 = gumbel_acc(u1);
            float s  = (g1 - g0) / (u1 - u0);
            g_gtab[i] = make_float2(s, g0 - s * u0);
        }
    } else if (b <= 480) {
        int i = (b - 1) * 256 + t;          // covers 384*320 exactly
        int k = i / N_V, n = i % N_V;
        float v = W[i];
        g_Wt_f32 [n * K_D + k] = v;
        g_Wt_bf16[n * K_D + k] = __float2bfloat16(v);
    } else {
        const int eb = b - 481;              // 0..239
        const int o0  = (eb % 12) * 64;
        const int gv0 = (eb / 12) * 32;
        const int ty = t >> 4, tx = t & 15;
        const int goff = (gv0 >= 320) ? 384 : 0;
        float acc0[4] = {0.f,0.f,0.f,0.f}, acc1[4] = {0.f,0.f,0.f,0.f};

        for (int k0 = 0; k0 < K_D; k0 += 16) {
            #pragma unroll
            for (int i = 0; i < 2; ++i) {
                int idx = t + i * 256;
                int r = idx >> 4, c = idx & 15;
                As2[r][c] = CB[(size_t)(gv0 + r) * K_D + k0 + c];
            }
            #pragma unroll
            for (int i = 0; i < 4; ++i) {
                int idx = t + i * 256;
                int r = idx >> 6, c = idx & 63;
                Bs2[r][c] = Wout[(size_t)(goff + k0 + r) * OUT_D + o0 + c];
            }
            __syncthreads();
            #pragma unroll
            for (int k = 0; k < 16; ++k) {
                float a0 = As2[ty][k], a1 = As2[ty + 16][k];
                #pragma unroll
                for (int j = 0; j < 4; ++j) {
                    float bb = Bs2[k][tx * 4 + j];
                    acc0[j] = fmaf(a0, bb, acc0[j]);
                    acc1[j] = fmaf(a1, bb, acc1[j]);
                }
            }
            __syncthreads();
        }
        #pragma unroll
        for (int j = 0; j < 4; ++j) {
            g_E[(size_t)(gv0 + ty)      * OUT_D + o0 + tx * 4 + j] = acc0[j];
            g_E[(size_t)(gv0 + ty + 16) * OUT_D + o0 + tx * 4 + j] = acc1[j];
        }
    }
}

// ---------------------------------------------------------------------------
// Kernel 0b: z fp32 -> bf16 (proven fastest A path)
// ---------------------------------------------------------------------------
__global__ __launch_bounds__(256) void convert_z_kernel(const float* __restrict__ z) {
    size_t base = ((size_t)blockIdx.x * 256 + threadIdx.x) * 8;
    float4 a = *reinterpret_cast<const float4*>(z + base);
    float4 b = *reinterpret_cast<const float4*>(z + base + 4);
    __nv_bfloat162 p0 = __floats2bfloat162_rn(a.x, a.y);
    __nv_bfloat162 p1 = __floats2bfloat162_rn(a.z, a.w);
    __nv_bfloat162 p2 = __floats2bfloat162_rn(b.x, b.y);
    __nv_bfloat162 p3 = __floats2bfloat162_rn(b.z, b.w);
    uint4 o;
    o.x = *reinterpret_cast<uint32_t*>(&p0);
    o.y = *reinterpret_cast<uint32_t*>(&p1);
    o.z = *reinterpret_cast<uint32_t*>(&p2);
    o.w = *reinterpret_cast<uint32_t*>(&p3);
    *reinterpret_cast<uint4*>(&g_z_bf16[base]) = o;
}

// ---------------------------------------------------------------------------
// Main kernel: R5 GEMM skeleton (BM=64, bf16 A, 3-stage cp.async, 512 thr)
//   + MUFU-free epilogue (bias-in-acc, smem gumbel table, value-only screen)
// ---------------------------------------------------------------------------
constexpr int STAGE_BYTES = 64 * 40 * 2 + 320 * 40 * 2;   // 30720
constexpr int SM_TAB      = 3 * STAGE_BYTES;              // 92160 (10240 B)
constexpr int SM_BESTV    = SM_TAB + 10240;               // 64 u32
constexpr int SM_CCNT     = SM_BESTV + 256;               // 64 int
constexpr int SM_IDXS     = SM_CCNT + 256;                // 64 int
constexpr int SM_CLIST    = SM_IDXS + 256;                // 64 x 8 int
constexpr int SMEM_MAIN   = SM_CLIST + 2048;              // 105216

__global__ __launch_bounds__(512, 1) void main_kernel(
    const float* __restrict__ z, const float* __restrict__ noise,
    const float* __restrict__ blog, const float* __restrict__ bout,
    float* __restrict__ out)
{
    extern __shared__ __align__(16) unsigned char sm[];
    const int tid  = threadIdx.x;
    const int lane = tid & 31, wid = tid >> 5;
    const int warp_m = wid & 3, warp_n = wid >> 2;
    const int row0 = blockIdx.x * 64;
    const int gid = lane >> 2, tig = lane & 3;

    float2*   tab    = (float2*)(sm + SM_TAB);
    uint32_t* bestvI = (uint32_t*)(sm + SM_BESTV);
    int*      ccnt   = (int*)(sm + SM_CCNT);
    int*      idxs   = (int*)(sm + SM_IDXS);
    int*      clist  = (int*)(sm + SM_CLIST);

    // stage gumbel table; init per-row state (synced inside mainloop)
    {
        const float* srcf = reinterpret_cast<const float*>(g_gtab);
        float* dstf = reinterpret_cast<float*>(tab);
        #pragma unroll
        for (int i = tid; i < 2560; i += 512) dstf[i] = srcf[i];
        if (tid < 64) { bestvI[tid] = 0u; ccnt[tid] = 0; }
    }

    // accumulators pre-seeded with logits bias (mma accumulates on top)
    float acc[10][4];
    #pragma unroll
    for (int t = 0; t < 10; ++t) {
        const int col = warp_n * 80 + t * 8 + 2 * tig;
        float b0 = __ldg(&blog[col]), b1 = __ldg(&blog[col + 1]);
        acc[t][0] = b0; acc[t][2] = b0;
        acc[t][1] = b1; acc[t][3] = b1;
    }

    auto As = [&](int s) { return (__nv_bfloat16*)(sm + s * STAGE_BYTES); };
    auto Ws = [&](int s) { return (__nv_bfloat16*)(sm + s * STAGE_BYTES + 5120); };

    auto issue = [&](int kt) {
        if (kt < 12) {
            const int k0 = kt * 32, s = kt % 3;
            if (tid < 256) {   // A tile: 64 rows x 32 bf16 = 256 x 16B
                int r = tid >> 2, c8 = (tid & 3) * 8;
                cp16(As(s) + r * 40 + c8, &g_z_bf16[(size_t)(row0 + r) * K_D + k0 + c8]);
            }
            #pragma unroll
            for (int i = 0; i < 3; ++i) {   // W tile: 320 x 32 = 1280 x 16B
                int idx = tid + i * 512;
                if (idx < 1280) {
                    int r = idx >> 2, c8 = (idx & 3) * 8;
                    cp16(Ws(s) + r * 40 + c8, &g_Wt_bf16[(size_t)r * K_D + k0 + c8]);
                }
            }
        }
        CP_COMMIT();
    };
    issue(0); issue(1);

    const int li = lane & 7, lj = lane >> 3;
    for (int kt = 0; kt < 12; ++kt) {
        CP_WAIT1();
        __syncthreads();
        issue(kt + 2);
        const __nv_bfloat16* A = As(kt % 3);
        const __nv_bfloat16* W = Ws(kt % 3);
        #pragma unroll
        for (int ks = 0; ks < 2; ++ks) {
            const int kk = ks * 16;
            uint32_t a[4];
            {
                int r = warp_m * 16 + (lj & 1) * 8 + li;
                int c = kk + (lj >> 1) * 8;
                ldsm_x4(a, &A[r * 40 + c]);
            }
            #pragma unroll
            for (int p = 0; p < 5; ++p) {
                uint32_t b[4];
                int r = warp_n * 80 + p * 16 + (lj >> 1) * 8 + li;
                int c = kk + (lj & 1) * 8;
                ldsm_x4(b, &W[r * 40 + c]);
                mma_bf16(acc[2 * p],     a, b);
                mma_bf16(acc[2 * p + 1], a, b + 2);
            }
        }
    }
    __syncthreads();

    // ---- Phase A: gumbel via smem secant table (zero MUFU) + row max -------
    auto gumbel_tab = [&](float u) -> float {
        uint32_t bits = __float_as_uint(u);
        uint32_t idx = (bits >> 16) - 14976u;
        if (idx > 1274u) return gumbel_acc(u);   // tiny u or u>~0.977
        float2 si = tab[idx];
        return fmaf(si.x, u, si.y);
    };

    #pragma unroll
    for (int h = 0; h < 2; ++h) {
        const int rl = warp_m * 16 + gid + 8 * h;
        const size_t gRow = row0 + rl;
        float best = -1e30f;
        #pragma unroll
        for (int t = 0; t < 10; ++t) {
            const int col = warp_n * 80 + t * 8 + 2 * tig;
            float2 u = *reinterpret_cast<const float2*>(&noise[gRow * N_V + col]);
            float v0 = acc[t][2*h]   + gumbel_tab(u.x);
            float v1 = acc[t][2*h+1] + gumbel_tab(u.y);
            acc[t][2*h] = v0; acc[t][2*h+1] = v1;
            best = fmaxf(best, fmaxf(v0, v1));
        }
        #pragma unroll
        for (int off = 1; off <= 2; off <<= 1)
            best = fmaxf(best, __shfl_xor_sync(0xffffffffu, best, off));
        if (tig == 0) atomicMax(&bestvI[rl], fkey(best));
    }
    __syncthreads();

    // ---- Phase C: candidate scan (includes the max itself) -----------------
    #pragma unroll
    for (int h = 0; h < 2; ++h) {
        const int rl = warp_m * 16 + gid + 8 * h;
        const float thr = funkey(bestvI[rl]) - MARGIN;
        #pragma unroll
        for (int t = 0; t < 10; ++t) {
            const int col = warp_n * 80 + t * 8 + 2 * tig;
            #pragma unroll
            for (int c2 = 0; c2 < 2; ++c2) {
                if (acc[t][2*h + c2] >= thr) {
                    int pos = atomicAdd(&ccnt[rl], 1);
                    if (pos < 8) clist[rl * 8 + pos] = col + c2;
                }
            }
        }
    }
    __syncthreads();

    // ---- Phase D: resolve; compensated-fp32 rescue for ambiguous rows ------
    for (int rl = wid; rl < 64; rl += 16) {
        const int nc = ccnt[rl];
        if (nc == 1) {
            if (lane == 0) idxs[rl] = clist[rl * 8];
            continue;
        }
        const size_t gRow = row0 + rl;
        const float* zr = &z[gRow * K_D];
        float bhi = -1e30f, blo = 0.f; int bbc = 0x7fffffff;

        auto score = [&](int col) {
            const float* wr = &g_Wt_f32[(size_t)col * K_D];
            float s = 0.f, c = 0.f;
            #pragma unroll
            for (int i = 0; i < 12; ++i) {
                int k = i * 32 + lane;
                float a = zr[k], b = wr[k];
                float p = a * b;
                float e = fmaf(a, b, -p);
                two_sum(s, c, p);
                c += e;
            }
            #pragma unroll
            for (int off = 16; off; off >>= 1) {
                float so = __shfl_xor_sync(0xffffffffu, s, off);
                float co = __shfl_xor_sync(0xffffffffu, c, off);
                two_sum(s, c, so);
                c += co;
            }
            float u = __ldg(&noise[gRow * N_V + col]);
            float base = __ldg(&blog[col]) + gumbel_acc(u);
            two_sum(s, c, base);
            bool gt = (s > bhi) || (s == bhi && (c > blo || (c == blo && col < bbc)));
            if (gt) { bhi = s; blo = c; bbc = col; }
        };

        if (nc > 8) {
            for (int col = 0; col < N_V; ++col) score(col);
        } else {
            for (int q = 0; q < nc; ++q) score(clist[rl * 8 + q]);
        }
        if (lane == 0) idxs[rl] = bbc;
    }
    __syncthreads();

    // ---- Phase E: fused output — 32 tokens: out = E[i0] + E[320+i1] + b_out
    {
        const int tl = tid >> 4;            // token 0..31
        const int j0 = tid & 15;
        const int i0 = idxs[2 * tl];
        const int i1 = idxs[2 * tl + 1];
        const float4* e0 = reinterpret_cast<const float4*>(&g_E[(size_t)i0 * OUT_D]);
        const float4* e1 = reinterpret_cast<const float4*>(&g_E[(size_t)(320 + i1) * OUT_D]);
        const float4* b4 = reinterpret_cast<const float4*>(bout);
        float4* o4 = reinterpret_cast<float4*>(&out[(size_t)(row0 / 2 + tl) * OUT_D]);
        #pragma unroll
        for (int c = j0; c < 192; c += 16) {
            float4 a = e0[c], b = e1[c], bb2 = b4[c];
            o4[c] = make_float4(a.x + b.x + bb2.x, a.y + b.y + bb2.y,
                                a.z + b.z + bb2.z, a.w + b.w + bb2.w);
        }
    }
}

// ---------------------------------------------------------------------------
extern "C" void kernel_launch(void* const* d_in, const int* in_sizes, int n_in,
                              void* d_out, int out_size)
{
    const float *z = nullptr, *noise = nullptr, *Wlog = nullptr, *blog = nullptr,
                *CB = nullptr, *Wout = nullptr, *bout = nullptr;
    for (int i = 0; i < n_in; ++i) {
        switch (in_sizes[i]) {
            case 25165824: z     = (const float*)d_in[i]; break;
            case 20971520: noise = (const float*)d_in[i]; break;
            case 122880:   Wlog  = (const float*)d_in[i]; break;
            case 320:      blog  = (const float*)d_in[i]; break;
            case 245760:   CB    = (const float*)d_in[i]; break;
            case 589824:   Wout  = (const float*)d_in[i]; break;
            case 768:      bout  = (const float*)d_in[i]; break;
        }
    }
    float* out = (float*)d_out;

    static bool attr_set = false;
    if (!attr_set) {
        cudaFuncSetAttribute(main_kernel,
            cudaFuncAttributeMaxDynamicSharedMemorySize, SMEM_MAIN);
        attr_set = true;
    }

    prep_kernel<<<721, 256>>>(Wlog, CB, Wout);
    convert_z_kernel<<<M_ROWS * K_D / (256 * 8), 256>>>(z);
    main_kernel<<<M_ROWS / 64, 512, SMEM_MAIN>>>(z, noise, blog, bout, out);
}

// round 16
// speedup vs baseline: 1.8579x; 1.8579x over previous
#include <cuda_runtime.h>
#include <cuda_bf16.h>
#include <cuda_fp16.h>
#include <cstdint>
#include <math.h>

// Problem constants
constexpr int M_ROWS = 65536;   // B*S*G
constexpr int N_V    = 320;
constexpr int K_D    = 384;
constexpr int OUT_D  = 768;
constexpr int GV     = 640;
constexpr float EPS_G  = 1e-10f;
constexpr float MARGIN = 0.43f;   // bf16 GEMM + fast-log + fp16 logits store

// Device-global scratch (no allocation allowed)
__device__ __nv_bfloat16 g_z_bf16[M_ROWS * K_D];   // 48MB
__device__ __half        g_logits[(size_t)M_ROWS * N_V]; // 42MB
__device__ __nv_bfloat16 g_Wt_bf16[N_V * K_D];     // W_logits^T bf16
__device__ float         g_Wt_f32 [N_V * K_D];     // W_logits^T fp32
__device__ float         g_E[GV * OUT_D];          // codebook@W_out fused table

__device__ __forceinline__ float gumbel_acc(float u) {
    return -logf(-logf(u + EPS_G) + EPS_G);
}
__device__ __forceinline__ float gumbel_fast(float u) {
    if (u > 0.999f) return gumbel_acc(u);   // rare accurate path
    float w = -__logf(u + EPS_G) + EPS_G;
    return -__logf(w);
}
__device__ __forceinline__ void two_sum(float& s, float& c, float v) {
    float t  = s + v;
    float bv = t - s;
    float err = (s - (t - bv)) + (v - bv);
    s = t; c += err;
}

__device__ __forceinline__ void ldsm_x4(uint32_t* r, const void* p) {
    uint32_t addr = (uint32_t)__cvta_generic_to_shared(p);
    asm volatile("ldmatrix.sync.aligned.m8n8.x4.shared.b16 {%0,%1,%2,%3}, [%4];\n"
        : "=r"(r[0]), "=r"(r[1]), "=r"(r[2]), "=r"(r[3]) : "r"(addr));
}
__device__ __forceinline__ void mma_bf16(float* c, const uint32_t* a, const uint32_t* b) {
    asm volatile("mma.sync.aligned.m16n8k16.row.col.f32.bf16.bf16.f32 "
        "{%0,%1,%2,%3}, {%4,%5,%6,%7}, {%8,%9}, {%0,%1,%2,%3};\n"
        : "+f"(c[0]), "+f"(c[1]), "+f"(c[2]), "+f"(c[3])
        : "r"(a[0]), "r"(a[1]), "r"(a[2]), "r"(a[3]), "r"(b[0]), "r"(b[1]));
}
__device__ __forceinline__ void cp16(void* dst_smem, const void* src) {
    uint32_t d = (uint32_t)__cvta_generic_to_shared(dst_smem);
    asm volatile("cp.async.cg.shared.global [%0], [%1], 16;\n" :: "r"(d), "l"(src));
}
#define CP_COMMIT() asm volatile("cp.async.commit_group;\n")
#define CP_WAIT1()  asm volatile("cp.async.wait_group 1;\n")

// ---------------------------------------------------------------------------
// Fused prep: b0..479 = W^T (bf16+fp32); b480..719 = E GEMM; b720.. = z->bf16
// ---------------------------------------------------------------------------
__global__ __launch_bounds__(256) void prep_kernel(
    const float* __restrict__ W, const float* __restrict__ CB,
    const float* __restrict__ Wout, const float* __restrict__ z)
{
    __shared__ float As2[32][17];
    __shared__ float Bs2[16][68];
    const int b = blockIdx.x;
    const int t = threadIdx.x;

    if (b < 480) {
        int i = b * 256 + t;                 // covers 384*320 exactly
        int k = i / N_V, n = i % N_V;
        float v = W[i];
        g_Wt_f32 [n * K_D + k] = v;
        g_Wt_bf16[n * K_D + k] = __float2bfloat16(v);
    } else if (b < 720) {
        const int eb = b - 480;              // 0..239
        const int o0  = (eb % 12) * 64;
        const int gv0 = (eb / 12) * 32;
        const int ty = t >> 4, tx = t & 15;
        const int goff = (gv0 >= 320) ? 384 : 0;
        float acc0[4] = {0.f,0.f,0.f,0.f}, acc1[4] = {0.f,0.f,0.f,0.f};

        for (int k0 = 0; k0 < K_D; k0 += 16) {
            #pragma unroll
            for (int i = 0; i < 2; ++i) {
                int idx = t + i * 256;
                int r = idx >> 4, c = idx & 15;
                As2[r][c] = CB[(size_t)(gv0 + r) * K_D + k0 + c];
            }
            #pragma unroll
            for (int i = 0; i < 4; ++i) {
                int idx = t + i * 256;
                int r = idx >> 6, c = idx & 63;
                Bs2[r][c] = Wout[(size_t)(goff + k0 + r) * OUT_D + o0 + c];
            }
            __syncthreads();
            #pragma unroll
            for (int k = 0; k < 16; ++k) {
                float a0 = As2[ty][k], a1 = As2[ty + 16][k];
                #pragma unroll
                for (int j = 0; j < 4; ++j) {
                    float bb = Bs2[k][tx * 4 + j];
                    acc0[j] = fmaf(a0, bb, acc0[j]);
                    acc1[j] = fmaf(a1, bb, acc1[j]);
                }
            }
            __syncthreads();
        }
        #pragma unroll
        for (int j = 0; j < 4; ++j) {
            g_E[(size_t)(gv0 + ty)      * OUT_D + o0 + tx * 4 + j] = acc0[j];
            g_E[(size_t)(gv0 + ty + 16) * OUT_D + o0 + tx * 4 + j] = acc1[j];
        }
    } else {
        size_t base = ((size_t)(b - 720) * 256 + t) * 8;
        float4 a = *reinterpret_cast<const float4*>(z + base);
        float4 c = *reinterpret_cast<const float4*>(z + base + 4);
        __nv_bfloat162 p0 = __floats2bfloat162_rn(a.x, a.y);
        __nv_bfloat162 p1 = __floats2bfloat162_rn(a.z, a.w);
        __nv_bfloat162 p2 = __floats2bfloat162_rn(c.x, c.y);
        __nv_bfloat162 p3 = __floats2bfloat162_rn(c.z, c.w);
        uint4 o;
        o.x = *reinterpret_cast<uint32_t*>(&p0);
        o.y = *reinterpret_cast<uint32_t*>(&p1);
        o.z = *reinterpret_cast<uint32_t*>(&p2);
        o.w = *reinterpret_cast<uint32_t*>(&p3);
        *reinterpret_cast<uint4*>(&g_z_bf16[base]) = o;
    }
}

// ---------------------------------------------------------------------------
// GEMM kernel: R5 mainloop (BM=64, 512 thr, 3-stage cp.async) -> fp16 logits
// ---------------------------------------------------------------------------
constexpr int STAGE_BYTES = 64 * 40 * 2 + 320 * 40 * 2;   // 30720
constexpr int SMEM_G      = 3 * STAGE_BYTES;              // 92160

__global__ __launch_bounds__(512, 1) void gemm_kernel()
{
    extern __shared__ __align__(16) unsigned char sm[];
    const int tid  = threadIdx.x;
    const int lane = tid & 31, wid = tid >> 5;
    const int warp_m = wid & 3, warp_n = wid >> 2;
    const int row0 = blockIdx.x * 64;

    float acc[10][4];
    #pragma unroll
    for (int t = 0; t < 10; ++t)
        #pragma unroll
        for (int j = 0; j < 4; ++j) acc[t][j] = 0.f;

    auto As = [&](int s) { return (__nv_bfloat16*)(sm + s * STAGE_BYTES); };
    auto Ws = [&](int s) { return (__nv_bfloat16*)(sm + s * STAGE_BYTES + 5120); };

    auto issue = [&](int kt) {
        if (kt < 12) {
            const int k0 = kt * 32, s = kt % 3;
            if (tid < 256) {   // A tile: 64 rows x 32 bf16 = 256 x 16B
                int r = tid >> 2, c8 = (tid & 3) * 8;
                cp16(As(s) + r * 40 + c8, &g_z_bf16[(size_t)(row0 + r) * K_D + k0 + c8]);
            }
            #pragma unroll
            for (int i = 0; i < 3; ++i) {   // W tile: 320 x 32 = 1280 x 16B
                int idx = tid + i * 512;
                if (idx < 1280) {
                    int r = idx >> 2, c8 = (idx & 3) * 8;
                    cp16(Ws(s) + r * 40 + c8, &g_Wt_bf16[(size_t)r * K_D + k0 + c8]);
                }
            }
        }
        CP_COMMIT();
    };
    issue(0); issue(1);

    const int li = lane & 7, lj = lane >> 3;
    for (int kt = 0; kt < 12; ++kt) {
        CP_WAIT1();
        __syncthreads();
        issue(kt + 2);
        const __nv_bfloat16* A = As(kt % 3);
        const __nv_bfloat16* W = Ws(kt % 3);
        #pragma unroll
        for (int ks = 0; ks < 2; ++ks) {
            const int kk = ks * 16;
            uint32_t a[4];
            {
                int r = warp_m * 16 + (lj & 1) * 8 + li;
                int c = kk + (lj >> 1) * 8;
                ldsm_x4(a, &A[r * 40 + c]);
            }
            #pragma unroll
            for (int p = 0; p < 5; ++p) {
                uint32_t b[4];
                int r = warp_n * 80 + p * 16 + (lj >> 1) * 8 + li;
                int c = kk + (lj & 1) * 8;
                ldsm_x4(b, &W[r * 40 + c]);
                mma_bf16(acc[2 * p],     a, b);
                mma_bf16(acc[2 * p + 1], a, b + 2);
            }
        }
    }

    // store logits fp16
    const int gid = lane >> 2, tig = lane & 3;
    const int r1 = warp_m * 16 + gid;
    const int r2 = r1 + 8;
    #pragma unroll
    for (int t = 0; t < 10; ++t) {
        const int col = warp_n * 80 + t * 8 + 2 * tig;
        __half2 lo = __floats2half2_rn(acc[t][0], acc[t][1]);
        __half2 hi = __floats2half2_rn(acc[t][2], acc[t][3]);
        *reinterpret_cast<__half2*>(&g_logits[(size_t)(row0 + r1) * N_V + col]) = lo;
        *reinterpret_cast<__half2*>(&g_logits[(size_t)(row0 + r2) * N_V + col]) = hi;
    }
}

// ---------------------------------------------------------------------------
// Epilogue kernel: 256 thr, high occupancy. Screen + rescue + fused output.
//   Each warp handles 8 rows; block covers 64 rows = 32 tokens.
// ---------------------------------------------------------------------------
__global__ __launch_bounds__(256) void ep_kernel(
    const float* __restrict__ z, const float* __restrict__ noise,
    const float* __restrict__ blog, const float* __restrict__ bout,
    float* __restrict__ out)
{
    __shared__ float blogS[N_V];
    __shared__ int   idxs[64];
    const int tid  = threadIdx.x;
    const int lane = tid & 31, wid = tid >> 5;
    const int row0 = blockIdx.x * 64;

    for (int i = tid; i < N_V; i += 256) blogS[i] = blog[i];
    __syncthreads();

    #pragma unroll 1
    for (int rr = 0; rr < 8; ++rr) {
        const int rl = wid * 8 + rr;
        const size_t gRow = row0 + rl;

        // lane owns cols [lane*10, lane*10+10)
        const int c0 = lane * 10;
        float l[10];
        {
            const __half2* Lp = reinterpret_cast<const __half2*>(
                &g_logits[gRow * N_V + c0]);   // 4B-aligned: c0 even
            #pragma unroll
            for (int j = 0; j < 5; ++j) {
                float2 f = __half22float2(Lp[j]);
                l[2*j] = f.x; l[2*j+1] = f.y;
            }
        }
        float u[10];
        {
            // float2 loads: (gRow*320 + lane*10)*4 bytes is always 8B-aligned
            const float2* Np = reinterpret_cast<const float2*>(&noise[gRow * N_V + c0]);
            #pragma unroll
            for (int j = 0; j < 5; ++j) {
                float2 f = Np[j];
                u[2*j] = f.x; u[2*j+1] = f.y;
            }
        }
        float v[10];
        float best = -1e30f; int bc = 0;
        #pragma unroll
        for (int j = 0; j < 10; ++j) {
            v[j] = l[j] + blogS[c0 + j] + gumbel_fast(u[j]);
            if (v[j] > best) { best = v[j]; bc = c0 + j; }
        }
        #pragma unroll
        for (int off = 16; off; off >>= 1) {
            float ov = __shfl_xor_sync(0xffffffffu, best, off);
            int   oc = __shfl_xor_sync(0xffffffffu, bc, off);
            if (ov > best || (ov == best && oc < bc)) { best = ov; bc = oc; }
        }
        const float thr = best - MARGIN;
        int cnt = 0;
        #pragma unroll
        for (int j = 0; j < 10; ++j) cnt += (v[j] >= thr) ? 1 : 0;
        #pragma unroll
        for (int off = 16; off; off >>= 1)
            cnt += __shfl_xor_sync(0xffffffffu, cnt, off);

        if (cnt <= 1) {
            if (lane == 0) idxs[rl] = bc;
            continue;
        }
        // rescue: exact compensated-fp32 rescoring of all candidates
        const float* zr = &z[gRow * K_D];
        float bhi = -1e30f, blo = 0.f; int bbc = 0x7fffffff;
        #pragma unroll 1
        for (int j = 0; j < 10; ++j) {
            unsigned ball = __ballot_sync(0xffffffffu, v[j] >= thr);
            while (ball) {
                int src = __ffs(ball) - 1; ball &= ball - 1;
                int col = src * 10 + j;
                const float* wr = &g_Wt_f32[(size_t)col * K_D];
                float s = 0.f, c = 0.f;
                #pragma unroll
                for (int i = 0; i < 12; ++i) {
                    int k = i * 32 + lane;
                    float a = zr[k], b = wr[k];
                    float p = a * b;
                    float e = fmaf(a, b, -p);
                    two_sum(s, c, p);
                    c += e;
                }
                #pragma unroll
                for (int off = 16; off; off >>= 1) {
                    float so = __shfl_xor_sync(0xffffffffu, s, off);
                    float co = __shfl_xor_sync(0xffffffffu, c, off);
                    two_sum(s, c, so);
                    c += co;
                }
                float uu = __ldg(&noise[gRow * N_V + col]);
                float base = blogS[col] + gumbel_acc(uu);
                two_sum(s, c, base);
                bool gt = (s > bhi) || (s == bhi && (c > blo || (c == blo && col < bbc)));
                if (gt) { bhi = s; blo = c; bbc = col; }
            }
        }
        if (lane == 0) idxs[rl] = bbc;
    }
    __syncthreads();

    // fused output: 32 tokens, out = E[i0] + E[320+i1] + b_out
    {
        const int tl = tid >> 3;            // token 0..31
        const int j0 = tid & 7;
        const int i0 = idxs[2 * tl];
        const int i1 = idxs[2 * tl + 1];
        const float4* e0 = reinterpret_cast<const float4*>(&g_E[(size_t)i0 * OUT_D]);
        const float4* e1 = reinterpret_cast<const float4*>(&g_E[(size_t)(320 + i1) * OUT_D]);
        const float4* b4 = reinterpret_cast<const float4*>(bout);
        float4* o4 = reinterpret_cast<float4*>(&out[(size_t)(row0 / 2 + tl) * OUT_D]);
        #pragma unroll
        for (int c = j0; c < 192; c += 8) {
            float4 a = e0[c], b = e1[c], bb2 = b4[c];
            o4[c] = make_float4(a.x + b.x + bb2.x, a.y + b.y + bb2.y,
                                a.z + b.z + bb2.z, a.w + b.w + bb2.w);
        }
    }
}

// ---------------------------------------------------------------------------
extern "C" void kernel_launch(void* const* d_in, const int* in_sizes, int n_in,
                              void* d_out, int out_size)
{
    const float *z = nullptr, *noise = nullptr, *Wlog = nullptr, *blog = nullptr,
                *CB = nullptr, *Wout = nullptr, *bout = nullptr;
    for (int i = 0; i < n_in; ++i) {
        switch (in_sizes[i]) {
            case 25165824: z     = (const float*)d_in[i]; break;
            case 20971520: noise = (const float*)d_in[i]; break;
            case 122880:   Wlog  = (const float*)d_in[i]; break;
            case 320:      blog  = (const float*)d_in[i]; break;
            case 245760:   CB    = (const float*)d_in[i]; break;
            case 589824:   Wout  = (const float*)d_in[i]; break;
            case 768:      bout  = (const float*)d_in[i]; break;
        }
    }
    float* out = (float*)d_out;

    static bool attr_set = false;
    if (!attr_set) {
        cudaFuncSetAttribute(gemm_kernel,
            cudaFuncAttributeMaxDynamicSharedMemorySize, SMEM_G);
        attr_set = true;
    }

    prep_kernel<<<720 + M_ROWS * K_D / (256 * 8), 256>>>(Wlog, CB, Wout, z);
    gemm_kernel<<<M_ROWS / 64, 512, SMEM_G>>>();
    ep_kernel<<<M_ROWS / 64, 256>>>(z, noise, blog, bout, out);
}